// round 14
// baseline (speedup 1.0000x reference)
#include <cuda_runtime.h>
#include <math.h>

#define Bn 256
#define Vn 6890
#define NJn 24
#define NBn 10
#define NPn 207
#define NJRn 43
#define Cn (Vn*3)       /* 20670 */
#define Cpad 20736      /* 81*256 */
#define KC2 218         /* 1 (vt) + 10 (beta) + 207 (pose) */
#define KCP 224         /* padded K: 14 chunks of 16 */
#define VSJ 48
#define VSEG 144

typedef unsigned long long ull;

__device__ __forceinline__ ull pk(float lo, float hi) {
    ull r; asm("mov.b64 %0,{%1,%2};" : "=l"(r) : "f"(lo), "f"(hi)); return r;
}
__device__ __forceinline__ void upk(ull v, float& lo, float& hi) {
    asm("mov.b64 {%0,%1},%2;" : "=f"(lo), "=f"(hi) : "l"(v));
}
__device__ __forceinline__ ull fma2(ull a, ull b, ull c) {
    ull d; asm("fma.rn.f32x2 %0,%1,%2,%3;" : "=l"(d) : "l"(a), "l"(b), "l"(c)); return d;
}
__device__ __forceinline__ ull mul2(ull a, ull b) {
    ull d; asm("mul.rn.f32x2 %0,%1,%2;" : "=l"(d) : "l"(a), "l"(b)); return d;
}

// ---------------- scratch ----------------------------------------------------
__device__ float g_coefT[KCP*Bn];            // [k][b]: row0=1, 1..10=beta, 11..217=pose, rest 0
__device__ float g_Rs[Bn*216];               // [b][24][9]
__device__ float g_A[Bn*NJn*12];
__device__ float g_prep[8*NJn*33];
__device__ float g_vposed[(size_t)Bn*Cpad];
__device__ float g_jpart[(size_t)VSJ*Bn*44*3];

__constant__ int PARc[NJn] = {0,0,0,0,1,2,3,4,5,6,7,8,9,9,9,12,13,14,16,17,18,19,20,21};
__constant__ int Lvl[9] = {1,4,7,10,15,18,20,22,24};

// ---------------- K0: Jr*vt and Jr*sd partial factors (vectorized, 2j/block)
__global__ void k_pre(const float* __restrict__ Jr, const float* __restrict__ vt,
                      const float* __restrict__ sd) {
    int j0 = blockIdx.x * 2;
    int s  = blockIdx.y;
    int vstart = s * 864;
    int vend = min(vstart + 864, Vn);
    int tid = threadIdx.x;

    float acc[2][33];
#pragma unroll
    for (int jj = 0; jj < 2; jj++)
#pragma unroll
        for (int e = 0; e < 33; e++) acc[jj][e] = 0.f;

    for (int v0 = vstart + tid*4; v0 < vend; v0 += 512) {
        if (v0 + 4 <= vend) {
            int c0 = v0*3;
            float4 t0 = *(const float4*)(vt + c0);
            float4 t1 = *(const float4*)(vt + c0 + 4);
            float4 t2 = *(const float4*)(vt + c0 + 8);
            float vv[12] = {t0.x,t0.y,t0.z,t0.w, t1.x,t1.y,t1.z,t1.w, t2.x,t2.y,t2.z,t2.w};
            float jr[2][4];
#pragma unroll
            for (int jj = 0; jj < 2; jj++) {
                const float* jp = Jr + (size_t)(j0+jj)*Vn + v0;
                float2 a = *(const float2*)jp;
                float2 b = *(const float2*)(jp + 2);
                jr[jj][0] = a.x; jr[jj][1] = a.y; jr[jj][2] = b.x; jr[jj][3] = b.y;
            }
#pragma unroll
            for (int e = 0; e < 12; e++) {
                int d = e % 3, g = e / 3;
                acc[0][d] += jr[0][g] * vv[e];
                acc[1][d] += jr[1][g] * vv[e];
            }
#pragma unroll
            for (int k = 0; k < NBn; k++) {
                const float* sp = sd + (size_t)k*Cn + c0;
                float2 s0 = *(const float2*)(sp + 0);
                float2 s1 = *(const float2*)(sp + 2);
                float2 s2 = *(const float2*)(sp + 4);
                float2 s3 = *(const float2*)(sp + 6);
                float2 s4 = *(const float2*)(sp + 8);
                float2 s5 = *(const float2*)(sp + 10);
                float sv[12] = {s0.x,s0.y,s1.x,s1.y,s2.x,s2.y,s3.x,s3.y,s4.x,s4.y,s5.x,s5.y};
#pragma unroll
                for (int e = 0; e < 12; e++) {
                    int d = e % 3, g = e / 3;
                    acc[0][3 + k*3 + d] += jr[0][g] * sv[e];
                    acc[1][3 + k*3 + d] += jr[1][g] * sv[e];
                }
            }
        } else {
            for (int v = v0; v < vend; v++) {
                float ja = Jr[(size_t)j0*Vn + v];
                float jb = Jr[(size_t)(j0+1)*Vn + v];
#pragma unroll
                for (int d = 0; d < 3; d++) {
                    float vd = vt[v*3 + d];
                    acc[0][d] += ja*vd; acc[1][d] += jb*vd;
                }
#pragma unroll
                for (int k = 0; k < NBn; k++)
#pragma unroll
                    for (int d = 0; d < 3; d++) {
                        float sdv = sd[(size_t)k*Cn + v*3 + d];
                        acc[0][3+k*3+d] += ja*sdv; acc[1][3+k*3+d] += jb*sdv;
                    }
            }
        }
    }
#pragma unroll
    for (int off = 16; off; off >>= 1)
#pragma unroll
        for (int jj = 0; jj < 2; jj++)
#pragma unroll
            for (int e = 0; e < 33; e++)
                acc[jj][e] += __shfl_down_sync(0xffffffffu, acc[jj][e], off);

    __shared__ float red[4][66];
    int w = tid >> 5, l = tid & 31;
    if (l == 0)
#pragma unroll
        for (int jj = 0; jj < 2; jj++)
#pragma unroll
            for (int e = 0; e < 33; e++) red[w][jj*33 + e] = acc[jj][e];
    __syncthreads();
    if (tid < 66) {
        float t = red[0][tid] + red[1][tid] + red[2][tid] + red[3][tid];
        int jj = tid / 33, e = tid % 33;
        g_prep[(s*NJn + (j0 + jj))*33 + e] = t;
    }
}

// ---------------- K1a: rodrigues + coefT (8 batches/block) --------------------
__global__ void k_rot(const float* __restrict__ beta, const float* __restrict__ theta) {
    __shared__ float Rsh[8][216];
    int w = threadIdx.x >> 5, lane = threadIdx.x & 31;
    int b = blockIdx.x*8 + w;

    if (lane < NJn) {
        int i = lane;
        float t0 = theta[b*72 + i*3 + 0];
        float t1 = theta[b*72 + i*3 + 1];
        float t2 = theta[b*72 + i*3 + 2];
        float a0 = t0 + 1e-8f, a1 = t1 + 1e-8f, a2 = t2 + 1e-8f;
        float angle = sqrtf(a0*a0 + a1*a1 + a2*a2);
        float inv = 1.0f / angle;
        float r0 = t0*inv, r1 = t1*inv, r2 = t2*inv;
        float s, c;
        sincosf(0.5f*angle, &s, &c);
        float qw = c, qx = s*r0, qy = s*r1, qz = s*r2;
        float qn = rsqrtf(qw*qw + qx*qx + qy*qy + qz*qz);
        qw *= qn; qx *= qn; qy *= qn; qz *= qn;
        float xx = qx*qx, yy = qy*qy, zz = qz*qz;
        float xy = qx*qy, xz = qx*qz, yz = qy*qz;
        float wx = qw*qx, wy = qw*qy, wz = qw*qz;
        Rsh[w][i*9+0] = 1.f - 2.f*(yy+zz); Rsh[w][i*9+1] = 2.f*(xy-wz);       Rsh[w][i*9+2] = 2.f*(xz+wy);
        Rsh[w][i*9+3] = 2.f*(xy+wz);       Rsh[w][i*9+4] = 1.f - 2.f*(xx+zz); Rsh[w][i*9+5] = 2.f*(yz-wx);
        Rsh[w][i*9+6] = 2.f*(xz-wy);       Rsh[w][i*9+7] = 2.f*(yz+wx);       Rsh[w][i*9+8] = 1.f - 2.f*(xx+yy);
    }
    __syncwarp();
    for (int i = lane; i < 216; i += 32)
        g_Rs[(size_t)b*216 + i] = Rsh[w][i];
    for (int idx = lane; idx < KCP; idx += 32) {
        float v = 0.f;
        if (idx == 0) v = 1.0f;
        else if (idx <= NBn) v = beta[b*NBn + idx - 1];
        else if (idx < KC2) {
            int e = idx - 11;
            int i = e / 9 + 1;
            int rr = e % 9;
            v = Rsh[w][i*9 + rr] - ((rr == 0 || rr == 4 || rr == 8) ? 1.f : 0.f);
        }
        g_coefT[idx*Bn + b] = v;
    }
}

// ---------------- K1b: J (reduces g_prep inline) + chain + A -------------------
__global__ void k_A(const float* __restrict__ beta) {
    int b = blockIdx.x;
    int t = threadIdx.x;          // 64 threads
    __shared__ float Rs[216];
    __shared__ float Jsh[72];
    __shared__ float G[288];
    __shared__ float JrF[33];     // reduced [JrVT(3) | JrSD(30)] per joint? no: per-j rows

    for (int i = t; i < 216; i += 64) Rs[i] = g_Rs[(size_t)b*216 + i];
    if (t < NJn) {
        int i = t;
        // reduce g_prep over 8 splits for joint i (33 values)
        float f[33];
#pragma unroll
        for (int e = 0; e < 33; e++) f[e] = 0.f;
#pragma unroll
        for (int ss = 0; ss < 8; ss++) {
            const float* gp = &g_prep[(ss*NJn + i)*33];
#pragma unroll
            for (int e = 0; e < 33; e++) f[e] += gp[e];
        }
#pragma unroll
        for (int d = 0; d < 3; d++) {
            float sj = f[d];
#pragma unroll
            for (int k = 0; k < NBn; k++)
                sj += beta[b*NBn + k] * f[3 + k*3 + d];
            Jsh[i*3 + d] = sj;
        }
    }
    (void)JrF;
    __syncthreads();
    if (t < 12) {
        int r = t >> 2, c = t & 3;
        float v;
        if (c < 3) v = Rs[r*3 + c] * (c == 0 ? 1.f : -1.f);
        else       v = Jsh[r];
        G[t] = v;
    }
    __syncthreads();
#pragma unroll
    for (int L = 0; L < 8; L++) {
        int s = Lvl[L], e = Lvl[L+1];
        int cnt = e - s;
        float val = 0.f;
        int i = 0, el = 0;
        bool act = t < cnt*12;
        if (act) {
            i = s + t/12; el = t - (i - s)*12;
            int r = el >> 2, c = el & 3;
            int p = PARc[i];
            val = (c == 3) ? G[p*12 + r*4 + 3] : 0.f;
#pragma unroll
            for (int m = 0; m < 3; m++) {
                float Lv = (c < 3) ? Rs[i*9 + m*3 + c] : (Jsh[i*3 + m] - Jsh[p*3 + m]);
                val += G[p*12 + r*4 + m] * Lv;
            }
        }
        if (act) G[i*12 + el] = val;
        __syncthreads();
    }
    if (t < NJn) {
        int i = t;
        float j0 = Jsh[i*3+0], j1 = Jsh[i*3+1], j2 = Jsh[i*3+2];
#pragma unroll
        for (int r = 0; r < 3; r++) {
            float g0 = G[i*12 + r*4 + 0], g1 = G[i*12 + r*4 + 1];
            float g2 = G[i*12 + r*4 + 2], g3 = G[i*12 + r*4 + 3];
            float* A = &g_A[((size_t)b*NJn + i)*12 + r*4];
            A[0] = g0; A[1] = g1; A[2] = g2;
            A[3] = g3 - (g0*j0 + g1*j1 + g2*j2);
        }
    }
}

// ---------------- K2: v_posed GEMM v10 — R9 tile, no prefetch, 3 blocks/SM ----
// block 128c x 128b, 256 thr, 8 warps; warp = 16c x 128b; thread = 16c x 4b
__global__ void __launch_bounds__(256, 3) k_vposed(const float* __restrict__ vt,
                                                   const float* __restrict__ sd,
                                                   const float* __restrict__ pd) {
    __shared__ float Ds[16][128];            // D tile: [k][c]
    __shared__ float Csh[16][128];           // coef tile: [k][b]
    __shared__ const float* Ptab[KCP];
    int cblk = blockIdx.x, bblk = blockIdx.y;
    int t = threadIdx.x, l = t & 31, w = t >> 5;
    int b0 = bblk*128;
    int c0 = cblk*128 + w*16;

    if (t < KCP) {
        const float* p;
        if (t == 0)       p = vt;
        else if (t <= 10) p = sd + (size_t)(t-1)*Cn;
        else if (t < KC2) p = pd + (size_t)(t-11)*Cn;
        else              p = vt;            // coef row is 0 -> contribution 0
        Ptab[t] = p;
    }

    ull acc[8][4];
#pragma unroll
    for (int cp = 0; cp < 8; cp++)
#pragma unroll
        for (int bb = 0; bb < 4; bb++) acc[cp][bb] = 0;

    int sr = t >> 4, sq = t & 15;            // staging: row 0..15, 8-float group
    int cg = cblk*128 + sq*8;
    bool ok8 = (cg + 8 <= Cn);
    const float* crow = g_coefT + (size_t)sr*Bn + b0 + sq*8;
    __syncthreads();                          // Ptab visible

    for (int kk = 0; kk < 14; kk++) {
        // stage chunk kk (loads issued after barrier; other blocks overlap)
        {
            const float* p = Ptab[kk*16 + sr];
            float v[8];
            if (ok8) {
#pragma unroll
                for (int q = 0; q < 4; q++) {
                    float2 a = *(const float2*)(p + cg + 2*q);
                    v[2*q] = a.x; v[2*q+1] = a.y;
                }
            } else {
#pragma unroll
                for (int e = 0; e < 8; e++) v[e] = (cg + e < Cn) ? p[cg + e] : 0.f;
            }
            const float* cr = crow + (size_t)kk*16*Bn;
            float4 ca = *(const float4*)(cr);
            float4 cb = *(const float4*)(cr + 4);
            *(float4*)&Ds[sr][sq*8 + 0] = make_float4(v[0], v[1], v[2], v[3]);
            *(float4*)&Ds[sr][sq*8 + 4] = make_float4(v[4], v[5], v[6], v[7]);
            *(float4*)&Csh[sr][sq*8 + 0] = ca;
            *(float4*)&Csh[sr][sq*8 + 4] = cb;
        }
        __syncthreads();
        // compute chunk
#pragma unroll
        for (int k = 0; k < 16; k++) {
            float4 cf = *(const float4*)&Csh[k][4*l];            // lane's 4 batches
            ull s0 = pk(cf.x, cf.x), s1 = pk(cf.y, cf.y);
            ull s2 = pk(cf.z, cf.z), s3 = pk(cf.w, cf.w);
            const ulonglong2* dp = (const ulonglong2*)&Ds[k][w*16];
            ulonglong2 dA = dp[0], dB = dp[1], dC = dp[2], dD = dp[3];
            acc[0][0] = fma2(dA.x, s0, acc[0][0]); acc[0][1] = fma2(dA.x, s1, acc[0][1]);
            acc[0][2] = fma2(dA.x, s2, acc[0][2]); acc[0][3] = fma2(dA.x, s3, acc[0][3]);
            acc[1][0] = fma2(dA.y, s0, acc[1][0]); acc[1][1] = fma2(dA.y, s1, acc[1][1]);
            acc[1][2] = fma2(dA.y, s2, acc[1][2]); acc[1][3] = fma2(dA.y, s3, acc[1][3]);
            acc[2][0] = fma2(dB.x, s0, acc[2][0]); acc[2][1] = fma2(dB.x, s1, acc[2][1]);
            acc[2][2] = fma2(dB.x, s2, acc[2][2]); acc[2][3] = fma2(dB.x, s3, acc[2][3]);
            acc[3][0] = fma2(dB.y, s0, acc[3][0]); acc[3][1] = fma2(dB.y, s1, acc[3][1]);
            acc[3][2] = fma2(dB.y, s2, acc[3][2]); acc[3][3] = fma2(dB.y, s3, acc[3][3]);
            acc[4][0] = fma2(dC.x, s0, acc[4][0]); acc[4][1] = fma2(dC.x, s1, acc[4][1]);
            acc[4][2] = fma2(dC.x, s2, acc[4][2]); acc[4][3] = fma2(dC.x, s3, acc[4][3]);
            acc[5][0] = fma2(dC.y, s0, acc[5][0]); acc[5][1] = fma2(dC.y, s1, acc[5][1]);
            acc[5][2] = fma2(dC.y, s2, acc[5][2]); acc[5][3] = fma2(dC.y, s3, acc[5][3]);
            acc[6][0] = fma2(dD.x, s0, acc[6][0]); acc[6][1] = fma2(dD.x, s1, acc[6][1]);
            acc[6][2] = fma2(dD.x, s2, acc[6][2]); acc[6][3] = fma2(dD.x, s3, acc[6][3]);
            acc[7][0] = fma2(dD.y, s0, acc[7][0]); acc[7][1] = fma2(dD.y, s1, acc[7][1]);
            acc[7][2] = fma2(dD.y, s2, acc[7][2]); acc[7][3] = fma2(dD.y, s3, acc[7][3]);
        }
        if (kk + 1 < 14) __syncthreads();     // before restaging
    }

    // epilogue: thread owns batches b0+4l..+3, cols c0..c0+15
#pragma unroll
    for (int bb = 0; bb < 4; bb++) {
        float* row = g_vposed + (size_t)(b0 + 4*l + bb)*Cpad + c0;
        float f[16];
#pragma unroll
        for (int cp = 0; cp < 8; cp++) upk(acc[cp][bb], f[2*cp], f[2*cp+1]);
#pragma unroll
        for (int q = 0; q < 4; q++)
            *(float4*)(row + 4*q) = make_float4(f[4*q], f[4*q+1], f[4*q+2], f[4*q+3]);
    }
}

// ---------------- K3: LBS skinning (4v x 1b per thread, warp=batch) ----------
__global__ void k_skin(const float* __restrict__ wts, float* __restrict__ out) {
    __shared__ float Wt[24][128];
    __shared__ float A_sh[8*288];
    int vblk = blockIdx.x, bblk = blockIdx.y;
    int tid = threadIdx.x;
    int lane = tid & 31, w = tid >> 5;
    int bg = bblk*8 + w;

    for (int idx = tid; idx < 128*24; idx += 256) {
        int v = idx / 24, j = idx % 24;
        int gv = vblk*128 + v;
        Wt[j][v] = (gv < Vn) ? wts[(size_t)gv*24 + j] : 0.f;
    }
    for (int idx = tid; idx < 8*288; idx += 256)
        A_sh[idx] = g_A[(size_t)bblk*8*288 + idx];
    __syncthreads();

    int v0 = vblk*128 + lane*4;

    ull m01[4][3], m23[4][3];
#pragma unroll
    for (int i = 0; i < 4; i++)
#pragma unroll
        for (int r = 0; r < 3; r++) { m01[i][r] = 0; m23[i][r] = 0; }

    const float* Ab = &A_sh[w*288];
#pragma unroll 4
    for (int j = 0; j < 24; j++) {
        float4 w4 = *(const float4*)&Wt[j][lane*4];
        ulonglong2 q0 = *(const ulonglong2*)&Ab[j*12 + 0];
        ulonglong2 q1 = *(const ulonglong2*)&Ab[j*12 + 4];
        ulonglong2 q2 = *(const ulonglong2*)&Ab[j*12 + 8];
        ull s0 = pk(w4.x, w4.x), s1 = pk(w4.y, w4.y);
        ull s2 = pk(w4.z, w4.z), s3 = pk(w4.w, w4.w);
        m01[0][0] = fma2(q0.x, s0, m01[0][0]); m23[0][0] = fma2(q0.y, s0, m23[0][0]);
        m01[0][1] = fma2(q1.x, s0, m01[0][1]); m23[0][1] = fma2(q1.y, s0, m23[0][1]);
        m01[0][2] = fma2(q2.x, s0, m01[0][2]); m23[0][2] = fma2(q2.y, s0, m23[0][2]);
        m01[1][0] = fma2(q0.x, s1, m01[1][0]); m23[1][0] = fma2(q0.y, s1, m23[1][0]);
        m01[1][1] = fma2(q1.x, s1, m01[1][1]); m23[1][1] = fma2(q1.y, s1, m23[1][1]);
        m01[1][2] = fma2(q2.x, s1, m01[1][2]); m23[1][2] = fma2(q2.y, s1, m23[1][2]);
        m01[2][0] = fma2(q0.x, s2, m01[2][0]); m23[2][0] = fma2(q0.y, s2, m23[2][0]);
        m01[2][1] = fma2(q1.x, s2, m01[2][1]); m23[2][1] = fma2(q1.y, s2, m23[2][1]);
        m01[2][2] = fma2(q2.x, s2, m01[2][2]); m23[2][2] = fma2(q2.y, s2, m23[2][2]);
        m01[3][0] = fma2(q0.x, s3, m01[3][0]); m23[3][0] = fma2(q0.y, s3, m23[3][0]);
        m01[3][1] = fma2(q1.x, s3, m01[3][1]); m23[3][1] = fma2(q1.y, s3, m23[3][1]);
        m01[3][2] = fma2(q2.x, s3, m01[3][2]); m23[3][2] = fma2(q2.y, s3, m23[3][2]);
    }

#pragma unroll
    for (int i = 0; i < 4; i++) {
        int v = v0 + i;
        if (v >= Vn) break;
        const float* vp = &g_vposed[(size_t)bg*Cpad + 3*v];
        float px = vp[0], py = vp[1], pz = vp[2];
        ull pxy = pk(px, py), pz1 = pk(pz, 1.0f);
        float* o = out + (size_t)bg*Cn + 3*v;
#pragma unroll
        for (int r = 0; r < 3; r++) {
            ull t = fma2(m01[i][r], pxy, mul2(m23[i][r], pz1));
            float lo, hi; upk(t, lo, hi);
            o[r] = lo + hi;
        }
    }
}

// ---------------- K4: joints partials (4j x 4b per thread) -------------------
__global__ void k_joints(const float* __restrict__ jr2, const float* __restrict__ out) {
    __shared__ float xs[3][32][68];
    __shared__ float jsh[32][48];
    const float* verts = out;
    int vs = blockIdx.x, bblk = blockIdx.y;
    int b0 = bblk*64;
    int vstart = vs*VSEG;
    int vend = min(vstart + VSEG, Vn);
    int tid = threadIdx.x;

    bool active = tid < 176;
    int jt = tid % 11, bt = tid / 11;

    ull acc[4][3][2];
#pragma unroll
    for (int jj = 0; jj < 4; jj++)
#pragma unroll
        for (int d = 0; d < 3; d++) { acc[jj][d][0] = 0; acc[jj][d][1] = 0; }

    for (int vbase = vstart; vbase < vend; vbase += 32) {
        int vcnt = min(32, vend - vbase);
        for (int idx = tid; idx < 64*96; idx += 192) {
            int b = idx / 96, e = idx % 96;
            int v = e / 3, d = e % 3;
            float val = (v < vcnt) ? verts[(size_t)(b0 + b)*Cn + (size_t)(vbase + v)*3 + d] : 0.f;
            xs[d][v][b] = val;
        }
        for (int idx = tid; idx < 44*32; idx += 192) {
            int j = idx >> 5, v = idx & 31;
            jsh[v][j] = (j < NJRn && v < vcnt) ? jr2[(size_t)j*Vn + vbase + v] : 0.f;
        }
        __syncthreads();
        if (active) {
#pragma unroll 4
            for (int v = 0; v < 32; v++) {
                float4 jr4 = *(const float4*)&jsh[v][jt*4];
                ull js0 = pk(jr4.x, jr4.x), js1 = pk(jr4.y, jr4.y);
                ull js2 = pk(jr4.z, jr4.z), js3 = pk(jr4.w, jr4.w);
#pragma unroll
                for (int d = 0; d < 3; d++) {
                    ulonglong2 xp = *(const ulonglong2*)&xs[d][v][bt*4];
                    acc[0][d][0] = fma2(xp.x, js0, acc[0][d][0]);
                    acc[0][d][1] = fma2(xp.y, js0, acc[0][d][1]);
                    acc[1][d][0] = fma2(xp.x, js1, acc[1][d][0]);
                    acc[1][d][1] = fma2(xp.y, js1, acc[1][d][1]);
                    acc[2][d][0] = fma2(xp.x, js2, acc[2][d][0]);
                    acc[2][d][1] = fma2(xp.y, js2, acc[2][d][1]);
                    acc[3][d][0] = fma2(xp.x, js3, acc[3][d][0]);
                    acc[3][d][1] = fma2(xp.y, js3, acc[3][d][1]);
                }
            }
        }
        __syncthreads();
    }
    if (active) {
#pragma unroll
        for (int jj = 0; jj < 4; jj++) {
            int j = jt*4 + jj;
#pragma unroll
            for (int d = 0; d < 3; d++) {
#pragma unroll
                for (int p = 0; p < 2; p++) {
                    float lo, hi;
                    upk(acc[jj][d][p], lo, hi);
                    int bA = b0 + bt*4 + 2*p;
                    g_jpart[((size_t)vs*Bn + bA)*132 + j*3 + d]     = lo;
                    g_jpart[((size_t)vs*Bn + bA + 1)*132 + j*3 + d] = hi;
                }
            }
        }
    }
}

// ---------------- K5: reduce joint partials ----------------------------------
__global__ void k_jred(float* __restrict__ out) {
    int i = blockIdx.x * blockDim.x + threadIdx.x;
    const int n = Bn*NJRn*3;
    if (i < n) {
        int b = i / 129, r = i % 129;
        float s = 0.f;
#pragma unroll 8
        for (int vs = 0; vs < VSJ; vs++)
            s += g_jpart[((size_t)vs*Bn + b)*132 + r];
        out[(size_t)Bn*Cn + i] = s;
    }
}

// ---------------- launch ------------------------------------------------------
extern "C" void kernel_launch(void* const* d_in, const int* in_sizes, int n_in,
                              void* d_out, int out_size) {
    const float* beta  = (const float*)d_in[0];
    const float* theta = (const float*)d_in[1];
    const float* vt    = (const float*)d_in[2];
    const float* sd    = (const float*)d_in[3];
    const float* pd    = (const float*)d_in[4];
    const float* Jr    = (const float*)d_in[5];
    const float* jr2   = (const float*)d_in[6];
    const float* wts   = (const float*)d_in[7];
    float* out = (float*)d_out;

    k_pre<<<dim3(12, 8), 128>>>(Jr, vt, sd);                  // 1
    k_rot<<<Bn/8, 256>>>(beta, theta);                        // 2
    k_A<<<Bn, 64>>>(beta);                                    // 3
    k_vposed<<<dim3(Cpad/128, Bn/128), 256>>>(vt, sd, pd);    // 4 (profiled slot)
    k_skin<<<dim3(54, 32), 256>>>(wts, out);                  // 5
    k_joints<<<dim3(VSJ, 4), 192>>>(jr2, out);                // 6
    k_jred<<<(Bn*NJRn*3 + 255)/256, 256>>>(out);              // 7
}

// round 15
// speedup vs baseline: 1.5322x; 1.5322x over previous
#include <cuda_runtime.h>
#include <math.h>

#define Bn 256
#define Vn 6890
#define NJn 24
#define NBn 10
#define NPn 207
#define NJRn 43
#define Cn (Vn*3)       /* 20670 */
#define Cpad 20736      /* 81*256 */
#define KC2 218         /* 1 (vt) + 10 (beta) + 207 (pose) */
#define KCP 224         /* padded K: 14 chunks of 16 */
#define VSJ 72
#define VSEG 96

typedef unsigned long long ull;

__device__ __forceinline__ ull pk(float lo, float hi) {
    ull r; asm("mov.b64 %0,{%1,%2};" : "=l"(r) : "f"(lo), "f"(hi)); return r;
}
__device__ __forceinline__ void upk(ull v, float& lo, float& hi) {
    asm("mov.b64 {%0,%1},%2;" : "=f"(lo), "=f"(hi) : "l"(v));
}
__device__ __forceinline__ ull fma2(ull a, ull b, ull c) {
    ull d; asm("fma.rn.f32x2 %0,%1,%2,%3;" : "=l"(d) : "l"(a), "l"(b), "l"(c)); return d;
}
__device__ __forceinline__ ull mul2(ull a, ull b) {
    ull d; asm("mul.rn.f32x2 %0,%1,%2;" : "=l"(d) : "l"(a), "l"(b)); return d;
}

// ---------------- scratch ----------------------------------------------------
__device__ float g_coefT[KCP*Bn];            // [k][b]: row0=1, 1..10=beta, 11..217=pose, rest 0
__device__ float g_Rs[Bn*216];               // [b][24][9]
__device__ float g_A[Bn*NJn*12];
__device__ float g_prep[8*NJn*33];
__device__ float g_JrSD[NJn*NBn*3];
__device__ float g_JrVT[NJn*3];
__device__ float g_vposed[(size_t)Bn*Cpad];
__device__ float g_jpart[(size_t)VSJ*Bn*44*3];

__constant__ int PARc[NJn] = {0,0,0,0,1,2,3,4,5,6,7,8,9,9,9,12,13,14,16,17,18,19,20,21};
__constant__ int Lvl[9] = {1,4,7,10,15,18,20,22,24};

// ---------------- K0a: Jr*vt and Jr*sd partial factors (vectorized, 2j/block)
__global__ void k_pre(const float* __restrict__ Jr, const float* __restrict__ vt,
                      const float* __restrict__ sd) {
    int j0 = blockIdx.x * 2;
    int s  = blockIdx.y;
    int vstart = s * 864;
    int vend = min(vstart + 864, Vn);
    int tid = threadIdx.x;

    float acc[2][33];
#pragma unroll
    for (int jj = 0; jj < 2; jj++)
#pragma unroll
        for (int e = 0; e < 33; e++) acc[jj][e] = 0.f;

    for (int v0 = vstart + tid*4; v0 < vend; v0 += 512) {
        if (v0 + 4 <= vend) {
            int c0 = v0*3;
            float4 t0 = *(const float4*)(vt + c0);
            float4 t1 = *(const float4*)(vt + c0 + 4);
            float4 t2 = *(const float4*)(vt + c0 + 8);
            float vv[12] = {t0.x,t0.y,t0.z,t0.w, t1.x,t1.y,t1.z,t1.w, t2.x,t2.y,t2.z,t2.w};
            float jr[2][4];
#pragma unroll
            for (int jj = 0; jj < 2; jj++) {
                const float* jp = Jr + (size_t)(j0+jj)*Vn + v0;
                float2 a = *(const float2*)jp;
                float2 b = *(const float2*)(jp + 2);
                jr[jj][0] = a.x; jr[jj][1] = a.y; jr[jj][2] = b.x; jr[jj][3] = b.y;
            }
#pragma unroll
            for (int e = 0; e < 12; e++) {
                int d = e % 3, g = e / 3;
                acc[0][d] += jr[0][g] * vv[e];
                acc[1][d] += jr[1][g] * vv[e];
            }
#pragma unroll
            for (int k = 0; k < NBn; k++) {
                const float* sp = sd + (size_t)k*Cn + c0;
                float2 s0 = *(const float2*)(sp + 0);
                float2 s1 = *(const float2*)(sp + 2);
                float2 s2 = *(const float2*)(sp + 4);
                float2 s3 = *(const float2*)(sp + 6);
                float2 s4 = *(const float2*)(sp + 8);
                float2 s5 = *(const float2*)(sp + 10);
                float sv[12] = {s0.x,s0.y,s1.x,s1.y,s2.x,s2.y,s3.x,s3.y,s4.x,s4.y,s5.x,s5.y};
#pragma unroll
                for (int e = 0; e < 12; e++) {
                    int d = e % 3, g = e / 3;
                    acc[0][3 + k*3 + d] += jr[0][g] * sv[e];
                    acc[1][3 + k*3 + d] += jr[1][g] * sv[e];
                }
            }
        } else {
            for (int v = v0; v < vend; v++) {
                float ja = Jr[(size_t)j0*Vn + v];
                float jb = Jr[(size_t)(j0+1)*Vn + v];
#pragma unroll
                for (int d = 0; d < 3; d++) {
                    float vd = vt[v*3 + d];
                    acc[0][d] += ja*vd; acc[1][d] += jb*vd;
                }
#pragma unroll
                for (int k = 0; k < NBn; k++)
#pragma unroll
                    for (int d = 0; d < 3; d++) {
                        float sdv = sd[(size_t)k*Cn + v*3 + d];
                        acc[0][3+k*3+d] += ja*sdv; acc[1][3+k*3+d] += jb*sdv;
                    }
            }
        }
    }
#pragma unroll
    for (int off = 16; off; off >>= 1)
#pragma unroll
        for (int jj = 0; jj < 2; jj++)
#pragma unroll
            for (int e = 0; e < 33; e++)
                acc[jj][e] += __shfl_down_sync(0xffffffffu, acc[jj][e], off);

    __shared__ float red[4][66];
    int w = tid >> 5, l = tid & 31;
    if (l == 0)
#pragma unroll
        for (int jj = 0; jj < 2; jj++)
#pragma unroll
            for (int e = 0; e < 33; e++) red[w][jj*33 + e] = acc[jj][e];
    __syncthreads();
    if (tid < 66) {
        float t = red[0][tid] + red[1][tid] + red[2][tid] + red[3][tid];
        int jj = tid / 33, e = tid % 33;
        g_prep[(s*NJn + (j0 + jj))*33 + e] = t;
    }
}

// ---------------- K0b: reduce partials ---------------------------------------
__global__ void k_pre2() {
    int i = blockIdx.x * blockDim.x + threadIdx.x;
    if (i < NJn*33) {
        int j = i / 33, e = i % 33;
        float s = 0.f;
#pragma unroll
        for (int ss = 0; ss < 8; ss++) s += g_prep[(ss*NJn + j)*33 + e];
        if (e < 3) g_JrVT[j*3 + e] = s;
        else       g_JrSD[j*30 + (e - 3)] = s;
    }
}

// ---------------- K1a: rodrigues + coefT (8 batches/block) --------------------
__global__ void k_rot(const float* __restrict__ beta, const float* __restrict__ theta) {
    __shared__ float Rsh[8][216];
    int w = threadIdx.x >> 5, lane = threadIdx.x & 31;
    int b = blockIdx.x*8 + w;

    if (lane < NJn) {
        int i = lane;
        float t0 = theta[b*72 + i*3 + 0];
        float t1 = theta[b*72 + i*3 + 1];
        float t2 = theta[b*72 + i*3 + 2];
        float a0 = t0 + 1e-8f, a1 = t1 + 1e-8f, a2 = t2 + 1e-8f;
        float angle = sqrtf(a0*a0 + a1*a1 + a2*a2);
        float inv = 1.0f / angle;
        float r0 = t0*inv, r1 = t1*inv, r2 = t2*inv;
        float s, c;
        sincosf(0.5f*angle, &s, &c);
        float qw = c, qx = s*r0, qy = s*r1, qz = s*r2;
        float qn = rsqrtf(qw*qw + qx*qx + qy*qy + qz*qz);
        qw *= qn; qx *= qn; qy *= qn; qz *= qn;
        float xx = qx*qx, yy = qy*qy, zz = qz*qz;
        float xy = qx*qy, xz = qx*qz, yz = qy*qz;
        float wx = qw*qx, wy = qw*qy, wz = qw*qz;
        Rsh[w][i*9+0] = 1.f - 2.f*(yy+zz); Rsh[w][i*9+1] = 2.f*(xy-wz);       Rsh[w][i*9+2] = 2.f*(xz+wy);
        Rsh[w][i*9+3] = 2.f*(xy+wz);       Rsh[w][i*9+4] = 1.f - 2.f*(xx+zz); Rsh[w][i*9+5] = 2.f*(yz-wx);
        Rsh[w][i*9+6] = 2.f*(xz-wy);       Rsh[w][i*9+7] = 2.f*(yz+wx);       Rsh[w][i*9+8] = 1.f - 2.f*(xx+yy);
    }
    __syncwarp();
    for (int i = lane; i < 216; i += 32)
        g_Rs[(size_t)b*216 + i] = Rsh[w][i];
    for (int idx = lane; idx < KCP; idx += 32) {
        float v = 0.f;
        if (idx == 0) v = 1.0f;
        else if (idx <= NBn) v = beta[b*NBn + idx - 1];
        else if (idx < KC2) {
            int e = idx - 11;
            int i = e / 9 + 1;
            int rr = e % 9;
            v = Rsh[w][i*9 + rr] - ((rr == 0 || rr == 4 || rr == 8) ? 1.f : 0.f);
        }
        g_coefT[idx*Bn + b] = v;
    }
}

// ---------------- K1b: J + level-parallel kinematic chain + A ------------------
__global__ void k_A(const float* __restrict__ beta) {
    int b = blockIdx.x;
    int t = threadIdx.x;          // 64 threads
    __shared__ float Rs[216];
    __shared__ float Jsh[72];
    __shared__ float G[288];

    for (int i = t; i < 216; i += 64) Rs[i] = g_Rs[(size_t)b*216 + i];
    if (t < NJn) {
        int i = t;
#pragma unroll
        for (int d = 0; d < 3; d++) {
            float sj = g_JrVT[i*3 + d];
#pragma unroll
            for (int k = 0; k < NBn; k++)
                sj += beta[b*NBn + k] * g_JrSD[i*30 + k*3 + d];
            Jsh[i*3 + d] = sj;
        }
    }
    __syncthreads();
    if (t < 12) {
        int r = t >> 2, c = t & 3;
        float v;
        if (c < 3) v = Rs[r*3 + c] * (c == 0 ? 1.f : -1.f);
        else       v = Jsh[r];
        G[t] = v;
    }
    __syncthreads();
#pragma unroll
    for (int L = 0; L < 8; L++) {
        int s = Lvl[L], e = Lvl[L+1];
        int cnt = e - s;
        float val = 0.f;
        int i = 0, el = 0;
        bool act = t < cnt*12;
        if (act) {
            i = s + t/12; el = t - (i - s)*12;
            int r = el >> 2, c = el & 3;
            int p = PARc[i];
            val = (c == 3) ? G[p*12 + r*4 + 3] : 0.f;
#pragma unroll
            for (int m = 0; m < 3; m++) {
                float Lv = (c < 3) ? Rs[i*9 + m*3 + c] : (Jsh[i*3 + m] - Jsh[p*3 + m]);
                val += G[p*12 + r*4 + m] * Lv;
            }
        }
        if (act) G[i*12 + el] = val;
        __syncthreads();
    }
    if (t < NJn) {
        int i = t;
        float j0 = Jsh[i*3+0], j1 = Jsh[i*3+1], j2 = Jsh[i*3+2];
#pragma unroll
        for (int r = 0; r < 3; r++) {
            float g0 = G[i*12 + r*4 + 0], g1 = G[i*12 + r*4 + 1];
            float g2 = G[i*12 + r*4 + 2], g3 = G[i*12 + r*4 + 3];
            float* A = &g_A[((size_t)b*NJn + i)*12 + r*4];
            A[0] = g0; A[1] = g1; A[2] = g2;
            A[3] = g3 - (g0*j0 + g1*j1 + g2*j2);
        }
    }
}

// ---------------- K2: v_posed GEMM (R9/v5) — smem coef + c-pair acc -----------
// block 128c x 128b, 256 thr, 8 warps; warp = 16c x 128b; thread = 16c x 4b
__global__ void __launch_bounds__(256, 2) k_vposed(const float* __restrict__ vt,
                                                   const float* __restrict__ sd,
                                                   const float* __restrict__ pd) {
    __shared__ float Ds[16][128];            // D tile: [k][c]
    __shared__ float Csh[16][128];           // coef tile: [k][b]
    __shared__ const float* Ptab[KCP];
    int cblk = blockIdx.x, bblk = blockIdx.y;
    int t = threadIdx.x, l = t & 31, w = t >> 5;
    int b0 = bblk*128;
    int c0 = cblk*128 + w*16;

    if (t < KCP) {
        const float* p;
        if (t == 0)       p = vt;
        else if (t <= 10) p = sd + (size_t)(t-1)*Cn;
        else if (t < KC2) p = pd + (size_t)(t-11)*Cn;
        else              p = vt;            // coef row is 0 -> contribution 0
        Ptab[t] = p;
    }

    ull acc[8][4];
#pragma unroll
    for (int cp = 0; cp < 8; cp++)
#pragma unroll
        for (int bb = 0; bb < 4; bb++) acc[cp][bb] = 0;

    int sr = t >> 4, sq = t & 15;            // staging coords: row 0..15, group 0..15
    int cg = cblk*128 + sq*8;
    bool ok8 = (cg + 8 <= Cn);
    const float* crow = g_coefT + (size_t)sr*Bn + b0 + sq*8;
    __syncthreads();                          // Ptab visible

    float dst[8], cst[8];
    // prefetch chunk 0
    {
        const float* p = Ptab[sr];
        if (ok8) {
#pragma unroll
            for (int q = 0; q < 4; q++) {
                float2 a = *(const float2*)(p + cg + 2*q);
                dst[2*q] = a.x; dst[2*q+1] = a.y;
            }
        } else {
#pragma unroll
            for (int e = 0; e < 8; e++) dst[e] = (cg + e < Cn) ? p[cg + e] : 0.f;
        }
        float4 ca = *(const float4*)(crow);
        float4 cb = *(const float4*)(crow + 4);
        cst[0]=ca.x; cst[1]=ca.y; cst[2]=ca.z; cst[3]=ca.w;
        cst[4]=cb.x; cst[5]=cb.y; cst[6]=cb.z; cst[7]=cb.w;
    }

    for (int kk = 0; kk < 14; kk++) {
        *(float4*)&Ds[sr][sq*8 + 0] = make_float4(dst[0], dst[1], dst[2], dst[3]);
        *(float4*)&Ds[sr][sq*8 + 4] = make_float4(dst[4], dst[5], dst[6], dst[7]);
        *(float4*)&Csh[sr][sq*8 + 0] = make_float4(cst[0], cst[1], cst[2], cst[3]);
        *(float4*)&Csh[sr][sq*8 + 4] = make_float4(cst[4], cst[5], cst[6], cst[7]);
        __syncthreads();
        if (kk + 1 < 14) {
            int k0n = (kk+1)*16;
            const float* p = Ptab[k0n + sr];
            if (ok8) {
#pragma unroll
                for (int q = 0; q < 4; q++) {
                    float2 a = *(const float2*)(p + cg + 2*q);
                    dst[2*q] = a.x; dst[2*q+1] = a.y;
                }
            } else {
#pragma unroll
                for (int e = 0; e < 8; e++) dst[e] = (cg + e < Cn) ? p[cg + e] : 0.f;
            }
            const float* cr = crow + (size_t)(kk+1)*16*Bn;
            float4 ca = *(const float4*)(cr);
            float4 cb = *(const float4*)(cr + 4);
            cst[0]=ca.x; cst[1]=ca.y; cst[2]=ca.z; cst[3]=ca.w;
            cst[4]=cb.x; cst[5]=cb.y; cst[6]=cb.z; cst[7]=cb.w;
        }
#pragma unroll
        for (int k = 0; k < 16; k++) {
            float4 cf = *(const float4*)&Csh[k][4*l];
            ull s0 = pk(cf.x, cf.x), s1 = pk(cf.y, cf.y);
            ull s2 = pk(cf.z, cf.z), s3 = pk(cf.w, cf.w);
            const ulonglong2* dp = (const ulonglong2*)&Ds[k][w*16];
            ulonglong2 dA = dp[0], dB = dp[1], dC = dp[2], dD = dp[3];
            acc[0][0] = fma2(dA.x, s0, acc[0][0]); acc[0][1] = fma2(dA.x, s1, acc[0][1]);
            acc[0][2] = fma2(dA.x, s2, acc[0][2]); acc[0][3] = fma2(dA.x, s3, acc[0][3]);
            acc[1][0] = fma2(dA.y, s0, acc[1][0]); acc[1][1] = fma2(dA.y, s1, acc[1][1]);
            acc[1][2] = fma2(dA.y, s2, acc[1][2]); acc[1][3] = fma2(dA.y, s3, acc[1][3]);
            acc[2][0] = fma2(dB.x, s0, acc[2][0]); acc[2][1] = fma2(dB.x, s1, acc[2][1]);
            acc[2][2] = fma2(dB.x, s2, acc[2][2]); acc[2][3] = fma2(dB.x, s3, acc[2][3]);
            acc[3][0] = fma2(dB.y, s0, acc[3][0]); acc[3][1] = fma2(dB.y, s1, acc[3][1]);
            acc[3][2] = fma2(dB.y, s2, acc[3][2]); acc[3][3] = fma2(dB.y, s3, acc[3][3]);
            acc[4][0] = fma2(dC.x, s0, acc[4][0]); acc[4][1] = fma2(dC.x, s1, acc[4][1]);
            acc[4][2] = fma2(dC.x, s2, acc[4][2]); acc[4][3] = fma2(dC.x, s3, acc[4][3]);
            acc[5][0] = fma2(dC.y, s0, acc[5][0]); acc[5][1] = fma2(dC.y, s1, acc[5][1]);
            acc[5][2] = fma2(dC.y, s2, acc[5][2]); acc[5][3] = fma2(dC.y, s3, acc[5][3]);
            acc[6][0] = fma2(dD.x, s0, acc[6][0]); acc[6][1] = fma2(dD.x, s1, acc[6][1]);
            acc[6][2] = fma2(dD.x, s2, acc[6][2]); acc[6][3] = fma2(dD.x, s3, acc[6][3]);
            acc[7][0] = fma2(dD.y, s0, acc[7][0]); acc[7][1] = fma2(dD.y, s1, acc[7][1]);
            acc[7][2] = fma2(dD.y, s2, acc[7][2]); acc[7][3] = fma2(dD.y, s3, acc[7][3]);
        }
        if (kk + 1 < 14) __syncthreads();
    }

#pragma unroll
    for (int bb = 0; bb < 4; bb++) {
        float* row = g_vposed + (size_t)(b0 + 4*l + bb)*Cpad + c0;
        float f[16];
#pragma unroll
        for (int cp = 0; cp < 8; cp++) upk(acc[cp][bb], f[2*cp], f[2*cp+1]);
#pragma unroll
        for (int q = 0; q < 4; q++)
            *(float4*)(row + 4*q) = make_float4(f[4*q], f[4*q+1], f[4*q+2], f[4*q+3]);
    }
}

// ---------------- K3: LBS skinning (4v x 1b per thread, warp=batch) ----------
__global__ void k_skin(const float* __restrict__ wts, float* __restrict__ out) {
    __shared__ float Wt[24][128];
    __shared__ float A_sh[8*288];
    int vblk = blockIdx.x, bblk = blockIdx.y;
    int tid = threadIdx.x;
    int lane = tid & 31, w = tid >> 5;
    int bg = bblk*8 + w;

    for (int idx = tid; idx < 128*24; idx += 256) {
        int v = idx / 24, j = idx % 24;
        int gv = vblk*128 + v;
        Wt[j][v] = (gv < Vn) ? wts[(size_t)gv*24 + j] : 0.f;
    }
    for (int idx = tid; idx < 8*288; idx += 256)
        A_sh[idx] = g_A[(size_t)bblk*8*288 + idx];
    __syncthreads();

    int v0 = vblk*128 + lane*4;

    ull m01[4][3], m23[4][3];
#pragma unroll
    for (int i = 0; i < 4; i++)
#pragma unroll
        for (int r = 0; r < 3; r++) { m01[i][r] = 0; m23[i][r] = 0; }

    const float* Ab = &A_sh[w*288];
#pragma unroll 4
    for (int j = 0; j < 24; j++) {
        float4 w4 = *(const float4*)&Wt[j][lane*4];
        ulonglong2 q0 = *(const ulonglong2*)&Ab[j*12 + 0];
        ulonglong2 q1 = *(const ulonglong2*)&Ab[j*12 + 4];
        ulonglong2 q2 = *(const ulonglong2*)&Ab[j*12 + 8];
        ull s0 = pk(w4.x, w4.x), s1 = pk(w4.y, w4.y);
        ull s2 = pk(w4.z, w4.z), s3 = pk(w4.w, w4.w);
        m01[0][0] = fma2(q0.x, s0, m01[0][0]); m23[0][0] = fma2(q0.y, s0, m23[0][0]);
        m01[0][1] = fma2(q1.x, s0, m01[0][1]); m23[0][1] = fma2(q1.y, s0, m23[0][1]);
        m01[0][2] = fma2(q2.x, s0, m01[0][2]); m23[0][2] = fma2(q2.y, s0, m23[0][2]);
        m01[1][0] = fma2(q0.x, s1, m01[1][0]); m23[1][0] = fma2(q0.y, s1, m23[1][0]);
        m01[1][1] = fma2(q1.x, s1, m01[1][1]); m23[1][1] = fma2(q1.y, s1, m23[1][1]);
        m01[1][2] = fma2(q2.x, s1, m01[1][2]); m23[1][2] = fma2(q2.y, s1, m23[1][2]);
        m01[2][0] = fma2(q0.x, s2, m01[2][0]); m23[2][0] = fma2(q0.y, s2, m23[2][0]);
        m01[2][1] = fma2(q1.x, s2, m01[2][1]); m23[2][1] = fma2(q1.y, s2, m23[2][1]);
        m01[2][2] = fma2(q2.x, s2, m01[2][2]); m23[2][2] = fma2(q2.y, s2, m23[2][2]);
        m01[3][0] = fma2(q0.x, s3, m01[3][0]); m23[3][0] = fma2(q0.y, s3, m23[3][0]);
        m01[3][1] = fma2(q1.x, s3, m01[3][1]); m23[3][1] = fma2(q1.y, s3, m23[3][1]);
        m01[3][2] = fma2(q2.x, s3, m01[3][2]); m23[3][2] = fma2(q2.y, s3, m23[3][2]);
    }

#pragma unroll
    for (int i = 0; i < 4; i++) {
        int v = v0 + i;
        if (v >= Vn) break;
        const float* vp = &g_vposed[(size_t)bg*Cpad + 3*v];
        float px = vp[0], py = vp[1], pz = vp[2];
        ull pxy = pk(px, py), pz1 = pk(pz, 1.0f);
        float* o = out + (size_t)bg*Cn + 3*v;
#pragma unroll
        for (int r = 0; r < 3; r++) {
            ull t = fma2(m01[i][r], pxy, mul2(m23[i][r], pz1));
            float lo, hi; upk(t, lo, hi);
            o[r] = lo + hi;
        }
    }
}

// ---------------- K4: joints partials (4j x 4b per thread) -------------------
__global__ void k_joints(const float* __restrict__ jr2, const float* __restrict__ out) {
    __shared__ float xs[3][32][68];
    __shared__ float jsh[32][48];
    const float* verts = out;
    int vs = blockIdx.x, bblk = blockIdx.y;
    int b0 = bblk*64;
    int vstart = vs*VSEG;
    int vend = min(vstart + VSEG, Vn);
    int tid = threadIdx.x;

    bool active = tid < 176;
    int jt = tid % 11, bt = tid / 11;

    ull acc[4][3][2];
#pragma unroll
    for (int jj = 0; jj < 4; jj++)
#pragma unroll
        for (int d = 0; d < 3; d++) { acc[jj][d][0] = 0; acc[jj][d][1] = 0; }

    for (int vbase = vstart; vbase < vend; vbase += 32) {
        int vcnt = min(32, vend - vbase);
        for (int idx = tid; idx < 64*96; idx += 192) {
            int b = idx / 96, e = idx % 96;
            int v = e / 3, d = e % 3;
            float val = (v < vcnt) ? verts[(size_t)(b0 + b)*Cn + (size_t)(vbase + v)*3 + d] : 0.f;
            xs[d][v][b] = val;
        }
        for (int idx = tid; idx < 44*32; idx += 192) {
            int j = idx >> 5, v = idx & 31;
            jsh[v][j] = (j < NJRn && v < vcnt) ? jr2[(size_t)j*Vn + vbase + v] : 0.f;
        }
        __syncthreads();
        if (active) {
#pragma unroll 4
            for (int v = 0; v < 32; v++) {
                float4 jr4 = *(const float4*)&jsh[v][jt*4];
                ull js0 = pk(jr4.x, jr4.x), js1 = pk(jr4.y, jr4.y);
                ull js2 = pk(jr4.z, jr4.z), js3 = pk(jr4.w, jr4.w);
#pragma unroll
                for (int d = 0; d < 3; d++) {
                    ulonglong2 xp = *(const ulonglong2*)&xs[d][v][bt*4];
                    acc[0][d][0] = fma2(xp.x, js0, acc[0][d][0]);
                    acc[0][d][1] = fma2(xp.y, js0, acc[0][d][1]);
                    acc[1][d][0] = fma2(xp.x, js1, acc[1][d][0]);
                    acc[1][d][1] = fma2(xp.y, js1, acc[1][d][1]);
                    acc[2][d][0] = fma2(xp.x, js2, acc[2][d][0]);
                    acc[2][d][1] = fma2(xp.y, js2, acc[2][d][1]);
                    acc[3][d][0] = fma2(xp.x, js3, acc[3][d][0]);
                    acc[3][d][1] = fma2(xp.y, js3, acc[3][d][1]);
                }
            }
        }
        __syncthreads();
    }
    if (active) {
#pragma unroll
        for (int jj = 0; jj < 4; jj++) {
            int j = jt*4 + jj;
#pragma unroll
            for (int d = 0; d < 3; d++) {
#pragma unroll
                for (int p = 0; p < 2; p++) {
                    float lo, hi;
                    upk(acc[jj][d][p], lo, hi);
                    int bA = b0 + bt*4 + 2*p;
                    g_jpart[((size_t)vs*Bn + bA)*132 + j*3 + d]     = lo;
                    g_jpart[((size_t)vs*Bn + bA + 1)*132 + j*3 + d] = hi;
                }
            }
        }
    }
}

// ---------------- K5: reduce joint partials ----------------------------------
__global__ void k_jred(float* __restrict__ out) {
    int i = blockIdx.x * blockDim.x + threadIdx.x;
    const int n = Bn*NJRn*3;
    if (i < n) {
        int b = i / 129, r = i % 129;
        float s = 0.f;
#pragma unroll 8
        for (int vs = 0; vs < VSJ; vs++)
            s += g_jpart[((size_t)vs*Bn + b)*132 + r];
        out[(size_t)Bn*Cn + i] = s;
    }
}

// ---------------- launch ------------------------------------------------------
extern "C" void kernel_launch(void* const* d_in, const int* in_sizes, int n_in,
                              void* d_out, int out_size) {
    const float* beta  = (const float*)d_in[0];
    const float* theta = (const float*)d_in[1];
    const float* vt    = (const float*)d_in[2];
    const float* sd    = (const float*)d_in[3];
    const float* pd    = (const float*)d_in[4];
    const float* Jr    = (const float*)d_in[5];
    const float* jr2   = (const float*)d_in[6];
    const float* wts   = (const float*)d_in[7];
    float* out = (float*)d_out;

    k_pre<<<dim3(12, 8), 128>>>(Jr, vt, sd);                  // 1
    k_pre2<<<(NJn*33 + 255)/256, 256>>>();                    // 2
    k_rot<<<Bn/8, 256>>>(beta, theta);                        // 3
    k_vposed<<<dim3(Cpad/128, Bn/128), 256>>>(vt, sd, pd);    // 4 (profiled slot)
    k_A<<<Bn, 64>>>(beta);                                    // 5
    k_skin<<<dim3(54, 32), 256>>>(wts, out);                  // 6
    k_joints<<<dim3(VSJ, 4), 192>>>(jr2, out);                // 7
    k_jred<<<(Bn*NJRn*3 + 255)/256, 256>>>(out);              // 8
}

// round 16
// speedup vs baseline: 1.5419x; 1.0063x over previous
#include <cuda_runtime.h>
#include <math.h>

#define Bn 256
#define Vn 6890
#define NJn 24
#define NBn 10
#define NPn 207
#define NJRn 43
#define Cn (Vn*3)       /* 20670 */
#define Cpad 20736      /* 81*256 */
#define KC2 218         /* 1 (vt) + 10 (beta) + 207 (pose) */
#define KCP 224         /* padded K: 14 chunks of 16 */
#define VSJ 72
#define VSEG 96

typedef unsigned long long ull;

__device__ __forceinline__ ull pk(float lo, float hi) {
    ull r; asm("mov.b64 %0,{%1,%2};" : "=l"(r) : "f"(lo), "f"(hi)); return r;
}
__device__ __forceinline__ void upk(ull v, float& lo, float& hi) {
    asm("mov.b64 {%0,%1},%2;" : "=f"(lo), "=f"(hi) : "l"(v));
}
__device__ __forceinline__ ull fma2(ull a, ull b, ull c) {
    ull d; asm("fma.rn.f32x2 %0,%1,%2,%3;" : "=l"(d) : "l"(a), "l"(b), "l"(c)); return d;
}
__device__ __forceinline__ ull mul2(ull a, ull b) {
    ull d; asm("mul.rn.f32x2 %0,%1,%2;" : "=l"(d) : "l"(a), "l"(b)); return d;
}

// ---------------- scratch ----------------------------------------------------
__device__ float g_coefT[KCP*Bn];            // [k][b]: row0=1, 1..10=beta, 11..217=pose, rest 0
__device__ float g_A[Bn*NJn*12];
__device__ float g_prep[8*NJn*33];
__device__ float g_vposed[(size_t)Bn*Cpad];
__device__ float g_jpart[(size_t)VSJ*Bn*44*3];

__constant__ int PARc[NJn] = {0,0,0,0,1,2,3,4,5,6,7,8,9,9,9,12,13,14,16,17,18,19,20,21};
__constant__ int Lvl[9] = {1,4,7,10,15,18,20,22,24};

// ---------------- K0: Jr*vt and Jr*sd partial factors (vectorized, 2j/block)
__global__ void k_pre(const float* __restrict__ Jr, const float* __restrict__ vt,
                      const float* __restrict__ sd) {
    int j0 = blockIdx.x * 2;
    int s  = blockIdx.y;
    int vstart = s * 864;
    int vend = min(vstart + 864, Vn);
    int tid = threadIdx.x;

    float acc[2][33];
#pragma unroll
    for (int jj = 0; jj < 2; jj++)
#pragma unroll
        for (int e = 0; e < 33; e++) acc[jj][e] = 0.f;

    for (int v0 = vstart + tid*4; v0 < vend; v0 += 512) {
        if (v0 + 4 <= vend) {
            int c0 = v0*3;
            float4 t0 = *(const float4*)(vt + c0);
            float4 t1 = *(const float4*)(vt + c0 + 4);
            float4 t2 = *(const float4*)(vt + c0 + 8);
            float vv[12] = {t0.x,t0.y,t0.z,t0.w, t1.x,t1.y,t1.z,t1.w, t2.x,t2.y,t2.z,t2.w};
            float jr[2][4];
#pragma unroll
            for (int jj = 0; jj < 2; jj++) {
                const float* jp = Jr + (size_t)(j0+jj)*Vn + v0;
                float2 a = *(const float2*)jp;
                float2 b = *(const float2*)(jp + 2);
                jr[jj][0] = a.x; jr[jj][1] = a.y; jr[jj][2] = b.x; jr[jj][3] = b.y;
            }
#pragma unroll
            for (int e = 0; e < 12; e++) {
                int d = e % 3, g = e / 3;
                acc[0][d] += jr[0][g] * vv[e];
                acc[1][d] += jr[1][g] * vv[e];
            }
#pragma unroll
            for (int k = 0; k < NBn; k++) {
                const float* sp = sd + (size_t)k*Cn + c0;
                float2 s0 = *(const float2*)(sp + 0);
                float2 s1 = *(const float2*)(sp + 2);
                float2 s2 = *(const float2*)(sp + 4);
                float2 s3 = *(const float2*)(sp + 6);
                float2 s4 = *(const float2*)(sp + 8);
                float2 s5 = *(const float2*)(sp + 10);
                float sv[12] = {s0.x,s0.y,s1.x,s1.y,s2.x,s2.y,s3.x,s3.y,s4.x,s4.y,s5.x,s5.y};
#pragma unroll
                for (int e = 0; e < 12; e++) {
                    int d = e % 3, g = e / 3;
                    acc[0][3 + k*3 + d] += jr[0][g] * sv[e];
                    acc[1][3 + k*3 + d] += jr[1][g] * sv[e];
                }
            }
        } else {
            for (int v = v0; v < vend; v++) {
                float ja = Jr[(size_t)j0*Vn + v];
                float jb = Jr[(size_t)(j0+1)*Vn + v];
#pragma unroll
                for (int d = 0; d < 3; d++) {
                    float vd = vt[v*3 + d];
                    acc[0][d] += ja*vd; acc[1][d] += jb*vd;
                }
#pragma unroll
                for (int k = 0; k < NBn; k++)
#pragma unroll
                    for (int d = 0; d < 3; d++) {
                        float sdv = sd[(size_t)k*Cn + v*3 + d];
                        acc[0][3+k*3+d] += ja*sdv; acc[1][3+k*3+d] += jb*sdv;
                    }
            }
        }
    }
#pragma unroll
    for (int off = 16; off; off >>= 1)
#pragma unroll
        for (int jj = 0; jj < 2; jj++)
#pragma unroll
            for (int e = 0; e < 33; e++)
                acc[jj][e] += __shfl_down_sync(0xffffffffu, acc[jj][e], off);

    __shared__ float red[4][66];
    int w = tid >> 5, l = tid & 31;
    if (l == 0)
#pragma unroll
        for (int jj = 0; jj < 2; jj++)
#pragma unroll
            for (int e = 0; e < 33; e++) red[w][jj*33 + e] = acc[jj][e];
    __syncthreads();
    if (tid < 66) {
        float t = red[0][tid] + red[1][tid] + red[2][tid] + red[3][tid];
        int jj = tid / 33, e = tid % 33;
        g_prep[(s*NJn + (j0 + jj))*33 + e] = t;
    }
}

// ---------------- K1: merged rodrigues + coefT + J + chain + A -----------------
__global__ void k_rotA(const float* __restrict__ beta, const float* __restrict__ theta) {
    int b = blockIdx.x;
    int t = threadIdx.x;          // 64 threads
    __shared__ float Rs[216];
    __shared__ float Jsh[72];
    __shared__ float G[288];

    if (t < NJn) {
        int i = t;
        float t0 = theta[b*72 + i*3 + 0];
        float t1 = theta[b*72 + i*3 + 1];
        float t2 = theta[b*72 + i*3 + 2];
        float a0 = t0 + 1e-8f, a1 = t1 + 1e-8f, a2 = t2 + 1e-8f;
        float angle = sqrtf(a0*a0 + a1*a1 + a2*a2);
        float inv = 1.0f / angle;
        float r0 = t0*inv, r1 = t1*inv, r2 = t2*inv;
        float s, c;
        sincosf(0.5f*angle, &s, &c);
        float qw = c, qx = s*r0, qy = s*r1, qz = s*r2;
        float qn = rsqrtf(qw*qw + qx*qx + qy*qy + qz*qz);
        qw *= qn; qx *= qn; qy *= qn; qz *= qn;
        float xx = qx*qx, yy = qy*qy, zz = qz*qz;
        float xy = qx*qy, xz = qx*qz, yz = qy*qz;
        float wx = qw*qx, wy = qw*qy, wz = qw*qz;
        Rs[i*9+0] = 1.f - 2.f*(yy+zz); Rs[i*9+1] = 2.f*(xy-wz);       Rs[i*9+2] = 2.f*(xz+wy);
        Rs[i*9+3] = 2.f*(xy+wz);       Rs[i*9+4] = 1.f - 2.f*(xx+zz); Rs[i*9+5] = 2.f*(yz-wx);
        Rs[i*9+6] = 2.f*(xz-wy);       Rs[i*9+7] = 2.f*(yz+wx);       Rs[i*9+8] = 1.f - 2.f*(xx+yy);
    }
    __syncthreads();
    // coefT[k][b]: row0 = 1 (vt), 1..10 beta, 11..217 pose, rest 0
    for (int idx = t; idx < KCP; idx += 64) {
        float v = 0.f;
        if (idx == 0) v = 1.0f;
        else if (idx <= NBn) v = beta[b*NBn + idx - 1];
        else if (idx < KC2) {
            int e = idx - 11;
            int i = e / 9 + 1;
            int rr = e % 9;
            v = Rs[i*9 + rr] - ((rr == 0 || rr == 4 || rr == 8) ? 1.f : 0.f);
        }
        g_coefT[idx*Bn + b] = v;
    }
    // J: reduce g_prep inline (R14-verified pattern)
    if (t < NJn) {
        int i = t;
        float f[33];
#pragma unroll
        for (int e = 0; e < 33; e++) f[e] = 0.f;
#pragma unroll
        for (int ss = 0; ss < 8; ss++) {
            const float* gp = &g_prep[(ss*NJn + i)*33];
#pragma unroll
            for (int e = 0; e < 33; e++) f[e] += gp[e];
        }
#pragma unroll
        for (int d = 0; d < 3; d++) {
            float sj = f[d];
#pragma unroll
            for (int k = 0; k < NBn; k++)
                sj += beta[b*NBn + k] * f[3 + k*3 + d];
            Jsh[i*3 + d] = sj;
        }
    }
    __syncthreads();
    if (t < 12) {
        int r = t >> 2, c = t & 3;
        float v;
        if (c < 3) v = Rs[r*3 + c] * (c == 0 ? 1.f : -1.f);
        else       v = Jsh[r];
        G[t] = v;
    }
    __syncthreads();
#pragma unroll
    for (int L = 0; L < 8; L++) {
        int s = Lvl[L], e = Lvl[L+1];
        int cnt = e - s;
        float val = 0.f;
        int i = 0, el = 0;
        bool act = t < cnt*12;
        if (act) {
            i = s + t/12; el = t - (i - s)*12;
            int r = el >> 2, c = el & 3;
            int p = PARc[i];
            val = (c == 3) ? G[p*12 + r*4 + 3] : 0.f;
#pragma unroll
            for (int m = 0; m < 3; m++) {
                float Lv = (c < 3) ? Rs[i*9 + m*3 + c] : (Jsh[i*3 + m] - Jsh[p*3 + m]);
                val += G[p*12 + r*4 + m] * Lv;
            }
        }
        if (act) G[i*12 + el] = val;
        __syncthreads();
    }
    if (t < NJn) {
        int i = t;
        float j0 = Jsh[i*3+0], j1 = Jsh[i*3+1], j2 = Jsh[i*3+2];
#pragma unroll
        for (int r = 0; r < 3; r++) {
            float g0 = G[i*12 + r*4 + 0], g1 = G[i*12 + r*4 + 1];
            float g2 = G[i*12 + r*4 + 2], g3 = G[i*12 + r*4 + 3];
            float* A = &g_A[((size_t)b*NJn + i)*12 + r*4];
            A[0] = g0; A[1] = g1; A[2] = g2;
            A[3] = g3 - (g0*j0 + g1*j1 + g2*j2);
        }
    }
}

// ---------------- K2: v_posed GEMM (R9/v5) — smem coef + c-pair acc -----------
__global__ void __launch_bounds__(256, 2) k_vposed(const float* __restrict__ vt,
                                                   const float* __restrict__ sd,
                                                   const float* __restrict__ pd) {
    __shared__ float Ds[16][128];
    __shared__ float Csh[16][128];
    __shared__ const float* Ptab[KCP];
    int cblk = blockIdx.x, bblk = blockIdx.y;
    int t = threadIdx.x, l = t & 31, w = t >> 5;
    int b0 = bblk*128;
    int c0 = cblk*128 + w*16;

    if (t < KCP) {
        const float* p;
        if (t == 0)       p = vt;
        else if (t <= 10) p = sd + (size_t)(t-1)*Cn;
        else if (t < KC2) p = pd + (size_t)(t-11)*Cn;
        else              p = vt;
        Ptab[t] = p;
    }

    ull acc[8][4];
#pragma unroll
    for (int cp = 0; cp < 8; cp++)
#pragma unroll
        for (int bb = 0; bb < 4; bb++) acc[cp][bb] = 0;

    int sr = t >> 4, sq = t & 15;
    int cg = cblk*128 + sq*8;
    bool ok8 = (cg + 8 <= Cn);
    const float* crow = g_coefT + (size_t)sr*Bn + b0 + sq*8;
    __syncthreads();

    float dst[8], cst[8];
    {
        const float* p = Ptab[sr];
        if (ok8) {
#pragma unroll
            for (int q = 0; q < 4; q++) {
                float2 a = *(const float2*)(p + cg + 2*q);
                dst[2*q] = a.x; dst[2*q+1] = a.y;
            }
        } else {
#pragma unroll
            for (int e = 0; e < 8; e++) dst[e] = (cg + e < Cn) ? p[cg + e] : 0.f;
        }
        float4 ca = *(const float4*)(crow);
        float4 cb = *(const float4*)(crow + 4);
        cst[0]=ca.x; cst[1]=ca.y; cst[2]=ca.z; cst[3]=ca.w;
        cst[4]=cb.x; cst[5]=cb.y; cst[6]=cb.z; cst[7]=cb.w;
    }

    for (int kk = 0; kk < 14; kk++) {
        *(float4*)&Ds[sr][sq*8 + 0] = make_float4(dst[0], dst[1], dst[2], dst[3]);
        *(float4*)&Ds[sr][sq*8 + 4] = make_float4(dst[4], dst[5], dst[6], dst[7]);
        *(float4*)&Csh[sr][sq*8 + 0] = make_float4(cst[0], cst[1], cst[2], cst[3]);
        *(float4*)&Csh[sr][sq*8 + 4] = make_float4(cst[4], cst[5], cst[6], cst[7]);
        __syncthreads();
        if (kk + 1 < 14) {
            int k0n = (kk+1)*16;
            const float* p = Ptab[k0n + sr];
            if (ok8) {
#pragma unroll
                for (int q = 0; q < 4; q++) {
                    float2 a = *(const float2*)(p + cg + 2*q);
                    dst[2*q] = a.x; dst[2*q+1] = a.y;
                }
            } else {
#pragma unroll
                for (int e = 0; e < 8; e++) dst[e] = (cg + e < Cn) ? p[cg + e] : 0.f;
            }
            const float* cr = crow + (size_t)(kk+1)*16*Bn;
            float4 ca = *(const float4*)(cr);
            float4 cb = *(const float4*)(cr + 4);
            cst[0]=ca.x; cst[1]=ca.y; cst[2]=ca.z; cst[3]=ca.w;
            cst[4]=cb.x; cst[5]=cb.y; cst[6]=cb.z; cst[7]=cb.w;
        }
#pragma unroll
        for (int k = 0; k < 16; k++) {
            float4 cf = *(const float4*)&Csh[k][4*l];
            ull s0 = pk(cf.x, cf.x), s1 = pk(cf.y, cf.y);
            ull s2 = pk(cf.z, cf.z), s3 = pk(cf.w, cf.w);
            const ulonglong2* dp = (const ulonglong2*)&Ds[k][w*16];
            ulonglong2 dA = dp[0], dB = dp[1], dC = dp[2], dD = dp[3];
            acc[0][0] = fma2(dA.x, s0, acc[0][0]); acc[0][1] = fma2(dA.x, s1, acc[0][1]);
            acc[0][2] = fma2(dA.x, s2, acc[0][2]); acc[0][3] = fma2(dA.x, s3, acc[0][3]);
            acc[1][0] = fma2(dA.y, s0, acc[1][0]); acc[1][1] = fma2(dA.y, s1, acc[1][1]);
            acc[1][2] = fma2(dA.y, s2, acc[1][2]); acc[1][3] = fma2(dA.y, s3, acc[1][3]);
            acc[2][0] = fma2(dB.x, s0, acc[2][0]); acc[2][1] = fma2(dB.x, s1, acc[2][1]);
            acc[2][2] = fma2(dB.x, s2, acc[2][2]); acc[2][3] = fma2(dB.x, s3, acc[2][3]);
            acc[3][0] = fma2(dB.y, s0, acc[3][0]); acc[3][1] = fma2(dB.y, s1, acc[3][1]);
            acc[3][2] = fma2(dB.y, s2, acc[3][2]); acc[3][3] = fma2(dB.y, s3, acc[3][3]);
            acc[4][0] = fma2(dC.x, s0, acc[4][0]); acc[4][1] = fma2(dC.x, s1, acc[4][1]);
            acc[4][2] = fma2(dC.x, s2, acc[4][2]); acc[4][3] = fma2(dC.x, s3, acc[4][3]);
            acc[5][0] = fma2(dC.y, s0, acc[5][0]); acc[5][1] = fma2(dC.y, s1, acc[5][1]);
            acc[5][2] = fma2(dC.y, s2, acc[5][2]); acc[5][3] = fma2(dC.y, s3, acc[5][3]);
            acc[6][0] = fma2(dD.x, s0, acc[6][0]); acc[6][1] = fma2(dD.x, s1, acc[6][1]);
            acc[6][2] = fma2(dD.x, s2, acc[6][2]); acc[6][3] = fma2(dD.x, s3, acc[6][3]);
            acc[7][0] = fma2(dD.y, s0, acc[7][0]); acc[7][1] = fma2(dD.y, s1, acc[7][1]);
            acc[7][2] = fma2(dD.y, s2, acc[7][2]); acc[7][3] = fma2(dD.y, s3, acc[7][3]);
        }
        if (kk + 1 < 14) __syncthreads();
    }

#pragma unroll
    for (int bb = 0; bb < 4; bb++) {
        float* row = g_vposed + (size_t)(b0 + 4*l + bb)*Cpad + c0;
        float f[16];
#pragma unroll
        for (int cp = 0; cp < 8; cp++) upk(acc[cp][bb], f[2*cp], f[2*cp+1]);
#pragma unroll
        for (int q = 0; q < 4; q++)
            *(float4*)(row + 4*q) = make_float4(f[4*q], f[4*q+1], f[4*q+2], f[4*q+3]);
    }
}

// ---------------- K3: LBS skinning (4v x 1b per thread, warp=batch) ----------
__global__ void k_skin(const float* __restrict__ wts, float* __restrict__ out) {
    __shared__ float Wt[24][128];
    __shared__ float A_sh[8*288];
    int vblk = blockIdx.x, bblk = blockIdx.y;
    int tid = threadIdx.x;
    int lane = tid & 31, w = tid >> 5;
    int bg = bblk*8 + w;

    for (int idx = tid; idx < 128*24; idx += 256) {
        int v = idx / 24, j = idx % 24;
        int gv = vblk*128 + v;
        Wt[j][v] = (gv < Vn) ? wts[(size_t)gv*24 + j] : 0.f;
    }
    for (int idx = tid; idx < 8*288; idx += 256)
        A_sh[idx] = g_A[(size_t)bblk*8*288 + idx];
    __syncthreads();

    int v0 = vblk*128 + lane*4;

    ull m01[4][3], m23[4][3];
#pragma unroll
    for (int i = 0; i < 4; i++)
#pragma unroll
        for (int r = 0; r < 3; r++) { m01[i][r] = 0; m23[i][r] = 0; }

    const float* Ab = &A_sh[w*288];
#pragma unroll 4
    for (int j = 0; j < 24; j++) {
        float4 w4 = *(const float4*)&Wt[j][lane*4];
        ulonglong2 q0 = *(const ulonglong2*)&Ab[j*12 + 0];
        ulonglong2 q1 = *(const ulonglong2*)&Ab[j*12 + 4];
        ulonglong2 q2 = *(const ulonglong2*)&Ab[j*12 + 8];
        ull s0 = pk(w4.x, w4.x), s1 = pk(w4.y, w4.y);
        ull s2 = pk(w4.z, w4.z), s3 = pk(w4.w, w4.w);
        m01[0][0] = fma2(q0.x, s0, m01[0][0]); m23[0][0] = fma2(q0.y, s0, m23[0][0]);
        m01[0][1] = fma2(q1.x, s0, m01[0][1]); m23[0][1] = fma2(q1.y, s0, m23[0][1]);
        m01[0][2] = fma2(q2.x, s0, m01[0][2]); m23[0][2] = fma2(q2.y, s0, m23[0][2]);
        m01[1][0] = fma2(q0.x, s1, m01[1][0]); m23[1][0] = fma2(q0.y, s1, m23[1][0]);
        m01[1][1] = fma2(q1.x, s1, m01[1][1]); m23[1][1] = fma2(q1.y, s1, m23[1][1]);
        m01[1][2] = fma2(q2.x, s1, m01[1][2]); m23[1][2] = fma2(q2.y, s1, m23[1][2]);
        m01[2][0] = fma2(q0.x, s2, m01[2][0]); m23[2][0] = fma2(q0.y, s2, m23[2][0]);
        m01[2][1] = fma2(q1.x, s2, m01[2][1]); m23[2][1] = fma2(q1.y, s2, m23[2][1]);
        m01[2][2] = fma2(q2.x, s2, m01[2][2]); m23[2][2] = fma2(q2.y, s2, m23[2][2]);
        m01[3][0] = fma2(q0.x, s3, m01[3][0]); m23[3][0] = fma2(q0.y, s3, m23[3][0]);
        m01[3][1] = fma2(q1.x, s3, m01[3][1]); m23[3][1] = fma2(q1.y, s3, m23[3][1]);
        m01[3][2] = fma2(q2.x, s3, m01[3][2]); m23[3][2] = fma2(q2.y, s3, m23[3][2]);
    }

#pragma unroll
    for (int i = 0; i < 4; i++) {
        int v = v0 + i;
        if (v >= Vn) break;
        const float* vp = &g_vposed[(size_t)bg*Cpad + 3*v];
        float px = vp[0], py = vp[1], pz = vp[2];
        ull pxy = pk(px, py), pz1 = pk(pz, 1.0f);
        float* o = out + (size_t)bg*Cn + 3*v;
#pragma unroll
        for (int r = 0; r < 3; r++) {
            ull t = fma2(m01[i][r], pxy, mul2(m23[i][r], pz1));
            float lo, hi; upk(t, lo, hi);
            o[r] = lo + hi;
        }
    }
}

// ---------------- K4: joints partials (4j x 4b per thread) -------------------
__global__ void k_joints(const float* __restrict__ jr2, const float* __restrict__ out) {
    __shared__ float xs[3][32][68];
    __shared__ float jsh[32][48];
    const float* verts = out;
    int vs = blockIdx.x, bblk = blockIdx.y;
    int b0 = bblk*64;
    int vstart = vs*VSEG;
    int vend = min(vstart + VSEG, Vn);
    int tid = threadIdx.x;

    bool active = tid < 176;
    int jt = tid % 11, bt = tid / 11;

    ull acc[4][3][2];
#pragma unroll
    for (int jj = 0; jj < 4; jj++)
#pragma unroll
        for (int d = 0; d < 3; d++) { acc[jj][d][0] = 0; acc[jj][d][1] = 0; }

    for (int vbase = vstart; vbase < vend; vbase += 32) {
        int vcnt = min(32, vend - vbase);
        for (int idx = tid; idx < 64*96; idx += 192) {
            int b = idx / 96, e = idx % 96;
            int v = e / 3, d = e % 3;
            float val = (v < vcnt) ? verts[(size_t)(b0 + b)*Cn + (size_t)(vbase + v)*3 + d] : 0.f;
            xs[d][v][b] = val;
        }
        for (int idx = tid; idx < 44*32; idx += 192) {
            int j = idx >> 5, v = idx & 31;
            jsh[v][j] = (j < NJRn && v < vcnt) ? jr2[(size_t)j*Vn + vbase + v] : 0.f;
        }
        __syncthreads();
        if (active) {
#pragma unroll 4
            for (int v = 0; v < 32; v++) {
                float4 jr4 = *(const float4*)&jsh[v][jt*4];
                ull js0 = pk(jr4.x, jr4.x), js1 = pk(jr4.y, jr4.y);
                ull js2 = pk(jr4.z, jr4.z), js3 = pk(jr4.w, jr4.w);
#pragma unroll
                for (int d = 0; d < 3; d++) {
                    ulonglong2 xp = *(const ulonglong2*)&xs[d][v][bt*4];
                    acc[0][d][0] = fma2(xp.x, js0, acc[0][d][0]);
                    acc[0][d][1] = fma2(xp.y, js0, acc[0][d][1]);
                    acc[1][d][0] = fma2(xp.x, js1, acc[1][d][0]);
                    acc[1][d][1] = fma2(xp.y, js1, acc[1][d][1]);
                    acc[2][d][0] = fma2(xp.x, js2, acc[2][d][0]);
                    acc[2][d][1] = fma2(xp.y, js2, acc[2][d][1]);
                    acc[3][d][0] = fma2(xp.x, js3, acc[3][d][0]);
                    acc[3][d][1] = fma2(xp.y, js3, acc[3][d][1]);
                }
            }
        }
        __syncthreads();
    }
    if (active) {
#pragma unroll
        for (int jj = 0; jj < 4; jj++) {
            int j = jt*4 + jj;
#pragma unroll
            for (int d = 0; d < 3; d++) {
#pragma unroll
                for (int p = 0; p < 2; p++) {
                    float lo, hi;
                    upk(acc[jj][d][p], lo, hi);
                    int bA = b0 + bt*4 + 2*p;
                    g_jpart[((size_t)vs*Bn + bA)*132 + j*3 + d]     = lo;
                    g_jpart[((size_t)vs*Bn + bA + 1)*132 + j*3 + d] = hi;
                }
            }
        }
    }
}

// ---------------- K5: reduce joint partials ----------------------------------
__global__ void k_jred(float* __restrict__ out) {
    int i = blockIdx.x * blockDim.x + threadIdx.x;
    const int n = Bn*NJRn*3;
    if (i < n) {
        int b = i / 129, r = i % 129;
        float s = 0.f;
#pragma unroll 8
        for (int vs = 0; vs < VSJ; vs++)
            s += g_jpart[((size_t)vs*Bn + b)*132 + r];
        out[(size_t)Bn*Cn + i] = s;
    }
}

// ---------------- launch ------------------------------------------------------
extern "C" void kernel_launch(void* const* d_in, const int* in_sizes, int n_in,
                              void* d_out, int out_size) {
    const float* beta  = (const float*)d_in[0];
    const float* theta = (const float*)d_in[1];
    const float* vt    = (const float*)d_in[2];
    const float* sd    = (const float*)d_in[3];
    const float* pd    = (const float*)d_in[4];
    const float* Jr    = (const float*)d_in[5];
    const float* jr2   = (const float*)d_in[6];
    const float* wts   = (const float*)d_in[7];
    float* out = (float*)d_out;

    k_pre<<<dim3(12, 8), 128>>>(Jr, vt, sd);                  // 1
    k_rotA<<<Bn, 64>>>(beta, theta);                          // 2
    k_vposed<<<dim3(Cpad/128, Bn/128), 256>>>(vt, sd, pd);    // 3
    k_skin<<<dim3(54, 32), 256>>>(wts, out);                  // 4 (profiled slot)
    k_joints<<<dim3(VSJ, 4), 192>>>(jr2, out);                // 5
    k_jred<<<(Bn*NJRn*3 + 255)/256, 256>>>(out);              // 6
}